// round 3
// baseline (speedup 1.0000x reference)
#include <cuda_runtime.h>

// Problem-size upper bounds (actual sizes taken from in_sizes at launch).
#define NMAX 100000

// -------- device scratch (no allocations allowed) --------
__device__ __align__(16) float g_dinv[NMAX];        // deg, then 1/sqrt(deg)
__device__ __align__(16) float g_h[NMAX * 16];      // x@W1, later reused as h1
__device__ __align__(16) float g_agg1[NMAX * 16];   // layer-1 aggregation
__device__ __align__(16) float g_agg2[NMAX * 16];   // layer-2 aggregation (pre-W2)
__device__ float g_s1[NMAX];                        // z . We[:64]
__device__ float g_s2[NMAX];                        // z . We[64:]
__device__ float g_v1[16];                          // W2 @ We[:64]
__device__ float g_v2[16];                          // W2 @ We[64:]
__device__ float g_c1, g_c2;                        // b2 . We halves

// -------- tiny precompute: fold W2/b2 into the edge head --------
__global__ void k_pre(const float* __restrict__ W2, const float* __restrict__ b2,
                      const float* __restrict__ We) {
    int t = threadIdx.x;
    if (t < 16) {
        float a = 0.f, b = 0.f;
        #pragma unroll
        for (int j = 0; j < 64; j++) {
            float w = W2[t * 64 + j];
            a += w * We[j];
            b += w * We[64 + j];
        }
        g_v1[t] = a;
        g_v2[t] = b;
    } else if (t == 16) {
        float a = 0.f, b = 0.f;
        #pragma unroll
        for (int j = 0; j < 64; j++) {
            a += b2[j] * We[j];
            b += b2[j] * We[64 + j];
        }
        g_c1 = a;
        g_c2 = b;
    }
}

// -------- degree + normalization --------
__global__ void k_deg_init(int n) {
    int i = blockIdx.x * blockDim.x + threadIdx.x;
    if (i < n) g_dinv[i] = 1.0f;   // self-loop
}

__global__ void k_deg_acc(const int* __restrict__ dst, int E, int n) {
    int e = blockIdx.x * blockDim.x + threadIdx.x;
    if (e < E) {
        unsigned d = (unsigned)dst[e];
        if (d < (unsigned)n) atomicAdd(&g_dinv[d], 1.0f);
    }
}

__global__ void k_dinv(int n) {
    int i = blockIdx.x * blockDim.x + threadIdx.x;
    if (i < n) g_dinv[i] = rsqrtf(g_dinv[i]);
}

// -------- GEMM1: h = x @ W1 ; agg1 = h * dinv^2 (self-loop term) --------
__global__ void k_gemm1(const float* __restrict__ x, const float* __restrict__ W1, int n) {
    __shared__ float4 Wss[512 * 4];   // W1[k][4q..4q+3]  (32 KB)
    for (int i = threadIdx.x; i < 2048; i += blockDim.x)
        Wss[i] = ((const float4*)W1)[i];
    __syncthreads();

    int r = blockIdx.x * blockDim.x + threadIdx.x;
    if (r >= n) return;

    float acc[16];
    #pragma unroll
    for (int j = 0; j < 16; j++) acc[j] = 0.f;

    const float4* xr = (const float4*)(x + (size_t)r * 512);
    #pragma unroll 4
    for (int k4 = 0; k4 < 128; k4++) {
        float4 xv = __ldg(&xr[k4]);
        #pragma unroll
        for (int kk = 0; kk < 4; kk++) {
            float xs = ((const float*)&xv)[kk];
            int kbase = (k4 * 4 + kk) * 4;
            #pragma unroll
            for (int q = 0; q < 4; q++) {
                float4 w = Wss[kbase + q];
                acc[q * 4 + 0] = fmaf(xs, w.x, acc[q * 4 + 0]);
                acc[q * 4 + 1] = fmaf(xs, w.y, acc[q * 4 + 1]);
                acc[q * 4 + 2] = fmaf(xs, w.z, acc[q * 4 + 2]);
                acc[q * 4 + 3] = fmaf(xs, w.w, acc[q * 4 + 3]);
            }
        }
    }

    float di = g_dinv[r];
    float sc = di * di;
    float4* hp = (float4*)(g_h + (size_t)r * 16);
    float4* ap = (float4*)(g_agg1 + (size_t)r * 16);
    #pragma unroll
    for (int q = 0; q < 4; q++) {
        float4 v = make_float4(acc[q * 4 + 0], acc[q * 4 + 1], acc[q * 4 + 2], acc[q * 4 + 3]);
        hp[q] = v;
        ap[q] = make_float4(v.x * sc, v.y * sc, v.z * sc, v.w * sc);
    }
}

// -------- 16-dim edge scatter: scalar global reductions (REDG.ADD.F32) --------
__device__ __forceinline__ void scatter_edge(const int* __restrict__ src,
                                             const int* __restrict__ dst,
                                             const float* __restrict__ h,
                                             float* __restrict__ agg, int e, int n) {
    unsigned s = (unsigned)src[e];
    unsigned d = (unsigned)dst[e];
    if (s >= (unsigned)n || d >= (unsigned)n) return;  // defensive: never trap
    float c = g_dinv[s] * g_dinv[d];
    const float4* hp = (const float4*)(h + (size_t)s * 16);
    float* ap = agg + (size_t)d * 16;
    #pragma unroll
    for (int q = 0; q < 4; q++) {
        float4 v = __ldg(&hp[q]);
        atomicAdd(ap + q * 4 + 0, v.x * c);
        atomicAdd(ap + q * 4 + 1, v.y * c);
        atomicAdd(ap + q * 4 + 2, v.z * c);
        atomicAdd(ap + q * 4 + 3, v.w * c);
    }
}

__global__ void k_scatter1(const int* __restrict__ src,
                           const int* __restrict__ dst, int E, int n) {
    int e = blockIdx.x * blockDim.x + threadIdx.x;
    if (e < E) scatter_edge(src, dst, g_h, g_agg1, e, n);
}

__global__ void k_scatter2(const int* __restrict__ src,
                           const int* __restrict__ dst, int E, int n) {
    int e = blockIdx.x * blockDim.x + threadIdx.x;
    if (e < E) scatter_edge(src, dst, g_h, g_agg2, e, n);  // g_h holds h1 here
}

// -------- relu(agg1 + b1) -> h1 (into g_h); seed agg2 with self-loop term --------
__global__ void k_relu(const float* __restrict__ b1, int n) {
    int i = blockIdx.x * blockDim.x + threadIdx.x;
    if (i >= n) return;
    float di = g_dinv[i];
    float sc = di * di;
    const float4* a = (const float4*)(g_agg1 + (size_t)i * 16);
    float4* h = (float4*)(g_h + (size_t)i * 16);
    float4* g2 = (float4*)(g_agg2 + (size_t)i * 16);
    const float4* b = (const float4*)b1;
    #pragma unroll
    for (int q = 0; q < 4; q++) {
        float4 v = a[q];
        float4 bb = __ldg(&b[q]);
        v.x = fmaxf(v.x + bb.x, 0.f);
        v.y = fmaxf(v.y + bb.y, 0.f);
        v.z = fmaxf(v.z + bb.z, 0.f);
        v.w = fmaxf(v.w + bb.w, 0.f);
        h[q] = v;
        g2[q] = make_float4(v.x * sc, v.y * sc, v.z * sc, v.w * sc);
    }
}

// -------- epilogue: z = agg2 @ W2 + b2 ; s1/s2 per-node head scalars --------
__global__ void k_out(const float* __restrict__ W2, const float* __restrict__ b2,
                      float* __restrict__ z, int n) {
    __shared__ float4 Ws[16 * 16];   // W2 rows as float4 quads (4 KB)
    __shared__ float4 bs[16];
    __shared__ float vs1[16], vs2[16];
    for (int i = threadIdx.x; i < 256; i += blockDim.x)
        Ws[i] = ((const float4*)W2)[i];
    if (threadIdx.x < 16) {
        bs[threadIdx.x] = ((const float4*)b2)[threadIdx.x];
        vs1[threadIdx.x] = g_v1[threadIdx.x];
        vs2[threadIdx.x] = g_v2[threadIdx.x];
    }
    __syncthreads();

    int r = blockIdx.x * blockDim.x + threadIdx.x;
    if (r >= n) return;

    float a[16];
    const float4* ag = (const float4*)(g_agg2 + (size_t)r * 16);
    #pragma unroll
    for (int q = 0; q < 4; q++) {
        float4 v = ag[q];
        a[q * 4 + 0] = v.x; a[q * 4 + 1] = v.y; a[q * 4 + 2] = v.z; a[q * 4 + 3] = v.w;
    }

    float s1 = g_c1, s2 = g_c2;
    #pragma unroll
    for (int k = 0; k < 16; k++) {
        s1 = fmaf(a[k], vs1[k], s1);
        s2 = fmaf(a[k], vs2[k], s2);
    }
    g_s1[r] = s1;
    g_s2[r] = s2;

    float4* zp = (float4*)(z + (size_t)r * 64);
    #pragma unroll
    for (int j4 = 0; j4 < 16; j4++) {
        float4 acc = bs[j4];
        #pragma unroll
        for (int k = 0; k < 16; k++) {
            float4 w = Ws[k * 16 + j4];
            acc.x = fmaf(a[k], w.x, acc.x);
            acc.y = fmaf(a[k], w.y, acc.y);
            acc.z = fmaf(a[k], w.z, acc.z);
            acc.w = fmaf(a[k], w.w, acc.w);
        }
        zp[j4] = acc;
    }
}

// -------- edge logits: s1[src] + s2[dst] + be --------
__global__ void k_logits(const int* __restrict__ ps, const int* __restrict__ pd,
                         const int* __restrict__ ns, const int* __restrict__ nd,
                         const float* __restrict__ be, float* __restrict__ out,
                         int P, int Ng, int n) {
    int i = blockIdx.x * blockDim.x + threadIdx.x;
    if (i >= P + Ng) return;
    unsigned s, d;
    if (i < P) { s = (unsigned)ps[i]; d = (unsigned)pd[i]; }
    else       { s = (unsigned)ns[i - P]; d = (unsigned)nd[i - P]; }
    float v = __ldg(be);
    if (s < (unsigned)n) v += g_s1[s];
    if (d < (unsigned)n) v += g_s2[d];
    out[i] = v;
}

extern "C" void kernel_launch(void* const* d_in, const int* in_sizes, int n_in,
                              void* d_out, int out_size) {
    const float* x  = (const float*)d_in[0];
    const float* W1 = (const float*)d_in[1];
    const float* b1 = (const float*)d_in[2];
    const float* W2 = (const float*)d_in[3];
    const float* b2 = (const float*)d_in[4];
    const float* We = (const float*)d_in[5];
    const float* be = (const float*)d_in[6];
    const int* ei = (const int*)d_in[7];   // edge_index as int32 [2, E]
    const int* pe = (const int*)d_in[8];   // pos_edge_index as int32 [2, P]
    const int* ne = (const int*)d_in[9];   // neg_edge_index as int32 [2, Ng]

    int n  = in_sizes[0] / 512;
    int E  = in_sizes[7] / 2;
    int P  = in_sizes[8] / 2;
    int Ng = in_sizes[9] / 2;

    float* z = (float*)d_out;                 // [n, 64]
    float* logits = z + (size_t)n * 64;       // [P + Ng]

    const int* src = ei;
    const int* dst = ei + E;

    int nb = (n + 255) / 256;
    int eb = (E + 255) / 256;
    int lb = (P + Ng + 255) / 256;

    k_pre<<<1, 32>>>(W2, b2, We);
    k_deg_init<<<nb, 256>>>(n);
    k_deg_acc<<<eb, 256>>>(dst, E, n);
    k_dinv<<<nb, 256>>>(n);
    k_gemm1<<<nb, 256>>>(x, W1, n);
    k_scatter1<<<eb, 256>>>(src, dst, E, n);
    k_relu<<<nb, 256>>>(b1, n);
    k_scatter2<<<eb, 256>>>(src, dst, E, n);
    k_out<<<nb, 256>>>(W2, b2, z, n);
    k_logits<<<lb, 256>>>(pe, pe + P, ne, ne + Ng, be, logits, P, Ng, n);
}

// round 4
// speedup vs baseline: 1.7781x; 1.7781x over previous
#include <cuda_runtime.h>

// Problem-size upper bounds (actual sizes taken from in_sizes at launch).
#define NMAX 100000

// -------- device scratch (no allocations allowed) --------
__device__ __align__(16) float g_dinv[NMAX];        // deg, then 1/sqrt(deg)
__device__ __align__(16) float g_h[NMAX * 16];      // x@W1, later reused as h1
__device__ __align__(16) float g_agg1[NMAX * 16];   // layer-1 aggregation
__device__ __align__(16) float g_agg2[NMAX * 16];   // layer-2 aggregation (pre-W2)
__device__ float g_s1[NMAX];                        // z . We[:64]
__device__ float g_s2[NMAX];                        // z . We[64:]
__device__ float g_v1[16];                          // W2 @ We[:64]
__device__ float g_v2[16];                          // W2 @ We[64:]
__device__ float g_c1, g_c2;                        // b2 . We halves

// -------- tiny precompute: fold W2/b2 into the edge head --------
__global__ void k_pre(const float* __restrict__ W2, const float* __restrict__ b2,
                      const float* __restrict__ We) {
    int t = threadIdx.x;
    if (t < 16) {
        float a = 0.f, b = 0.f;
        #pragma unroll
        for (int j = 0; j < 64; j++) {
            float w = W2[t * 64 + j];
            a += w * We[j];
            b += w * We[64 + j];
        }
        g_v1[t] = a;
        g_v2[t] = b;
    } else if (t == 16) {
        float a = 0.f, b = 0.f;
        #pragma unroll
        for (int j = 0; j < 64; j++) {
            a += b2[j] * We[j];
            b += b2[j] * We[64 + j];
        }
        g_c1 = a;
        g_c2 = b;
    }
}

// -------- degree + normalization --------
__global__ void k_deg_init(int n) {
    int i = blockIdx.x * blockDim.x + threadIdx.x;
    if (i < n) g_dinv[i] = 1.0f;   // self-loop
}

__global__ void k_deg_acc(const int* __restrict__ dst, int E, int n) {
    int e = blockIdx.x * blockDim.x + threadIdx.x;
    if (e < E) {
        unsigned d = (unsigned)dst[e];
        if (d < (unsigned)n) atomicAdd(&g_dinv[d], 1.0f);
    }
}

__global__ void k_dinv(int n) {
    int i = blockIdx.x * blockDim.x + threadIdx.x;
    if (i < n) g_dinv[i] = rsqrtf(g_dinv[i]);
}

// -------- GEMM1: h = x @ W1 ; agg1 = h * dinv^2 (self-loop term) --------
__global__ void k_gemm1(const float* __restrict__ x, const float* __restrict__ W1, int n) {
    __shared__ float4 Wss[512 * 4];   // W1[k][4q..4q+3]  (32 KB)
    for (int i = threadIdx.x; i < 2048; i += blockDim.x)
        Wss[i] = ((const float4*)W1)[i];
    __syncthreads();

    int r = blockIdx.x * blockDim.x + threadIdx.x;
    if (r >= n) return;

    float acc[16];
    #pragma unroll
    for (int j = 0; j < 16; j++) acc[j] = 0.f;

    const float4* xr = (const float4*)(x + (size_t)r * 512);
    #pragma unroll 4
    for (int k4 = 0; k4 < 128; k4++) {
        float4 xv = __ldg(&xr[k4]);
        #pragma unroll
        for (int kk = 0; kk < 4; kk++) {
            float xs = ((const float*)&xv)[kk];
            int kbase = (k4 * 4 + kk) * 4;
            #pragma unroll
            for (int q = 0; q < 4; q++) {
                float4 w = Wss[kbase + q];
                acc[q * 4 + 0] = fmaf(xs, w.x, acc[q * 4 + 0]);
                acc[q * 4 + 1] = fmaf(xs, w.y, acc[q * 4 + 1]);
                acc[q * 4 + 2] = fmaf(xs, w.z, acc[q * 4 + 2]);
                acc[q * 4 + 3] = fmaf(xs, w.w, acc[q * 4 + 3]);
            }
        }
    }

    float di = g_dinv[r];
    float sc = di * di;
    float4* hp = (float4*)(g_h + (size_t)r * 16);
    float4* ap = (float4*)(g_agg1 + (size_t)r * 16);
    #pragma unroll
    for (int q = 0; q < 4; q++) {
        float4 v = make_float4(acc[q * 4 + 0], acc[q * 4 + 1], acc[q * 4 + 2], acc[q * 4 + 3]);
        hp[q] = v;
        ap[q] = make_float4(v.x * sc, v.y * sc, v.z * sc, v.w * sc);
    }
}

// -------- 16-dim edge scatter: vector L2 reductions (4x red.v4.f32/edge) --------
__device__ __forceinline__ void scatter_edge(const int* __restrict__ src,
                                             const int* __restrict__ dst,
                                             const float* __restrict__ h,
                                             float* __restrict__ agg, int e, int n) {
    unsigned s = (unsigned)src[e];
    unsigned d = (unsigned)dst[e];
    if (s >= (unsigned)n || d >= (unsigned)n) return;  // defensive: never trap
    float c = g_dinv[s] * g_dinv[d];
    const float4* hp = (const float4*)(h + (size_t)s * 16);
    float* ap = agg + (size_t)d * 16;
    #pragma unroll
    for (int q = 0; q < 4; q++) {
        float4 v = __ldg(&hp[q]);
        asm volatile("red.global.add.v4.f32 [%0], {%1,%2,%3,%4};"
                     :: "l"(ap + q * 4), "f"(v.x * c), "f"(v.y * c), "f"(v.z * c), "f"(v.w * c)
                     : "memory");
    }
}

__global__ void k_scatter1(const int* __restrict__ src,
                           const int* __restrict__ dst, int E, int n) {
    int e = blockIdx.x * blockDim.x + threadIdx.x;
    if (e < E) scatter_edge(src, dst, g_h, g_agg1, e, n);
}

__global__ void k_scatter2(const int* __restrict__ src,
                           const int* __restrict__ dst, int E, int n) {
    int e = blockIdx.x * blockDim.x + threadIdx.x;
    if (e < E) scatter_edge(src, dst, g_h, g_agg2, e, n);  // g_h holds h1 here
}

// -------- relu(agg1 + b1) -> h1 (into g_h); seed agg2 with self-loop term --------
__global__ void k_relu(const float* __restrict__ b1, int n) {
    int i = blockIdx.x * blockDim.x + threadIdx.x;
    if (i >= n) return;
    float di = g_dinv[i];
    float sc = di * di;
    const float4* a = (const float4*)(g_agg1 + (size_t)i * 16);
    float4* h = (float4*)(g_h + (size_t)i * 16);
    float4* g2 = (float4*)(g_agg2 + (size_t)i * 16);
    const float4* b = (const float4*)b1;
    #pragma unroll
    for (int q = 0; q < 4; q++) {
        float4 v = a[q];
        float4 bb = __ldg(&b[q]);
        v.x = fmaxf(v.x + bb.x, 0.f);
        v.y = fmaxf(v.y + bb.y, 0.f);
        v.z = fmaxf(v.z + bb.z, 0.f);
        v.w = fmaxf(v.w + bb.w, 0.f);
        h[q] = v;
        g2[q] = make_float4(v.x * sc, v.y * sc, v.z * sc, v.w * sc);
    }
}

// -------- epilogue: z = agg2 @ W2 + b2 ; s1/s2 per-node head scalars --------
__global__ void k_out(const float* __restrict__ W2, const float* __restrict__ b2,
                      float* __restrict__ z, int n) {
    __shared__ float4 Ws[16 * 16];   // W2 rows as float4 quads (4 KB)
    __shared__ float4 bs[16];
    __shared__ float vs1[16], vs2[16];
    for (int i = threadIdx.x; i < 256; i += blockDim.x)
        Ws[i] = ((const float4*)W2)[i];
    if (threadIdx.x < 16) {
        bs[threadIdx.x] = ((const float4*)b2)[threadIdx.x];
        vs1[threadIdx.x] = g_v1[threadIdx.x];
        vs2[threadIdx.x] = g_v2[threadIdx.x];
    }
    __syncthreads();

    int r = blockIdx.x * blockDim.x + threadIdx.x;
    if (r >= n) return;

    float a[16];
    const float4* ag = (const float4*)(g_agg2 + (size_t)r * 16);
    #pragma unroll
    for (int q = 0; q < 4; q++) {
        float4 v = ag[q];
        a[q * 4 + 0] = v.x; a[q * 4 + 1] = v.y; a[q * 4 + 2] = v.z; a[q * 4 + 3] = v.w;
    }

    float s1 = g_c1, s2 = g_c2;
    #pragma unroll
    for (int k = 0; k < 16; k++) {
        s1 = fmaf(a[k], vs1[k], s1);
        s2 = fmaf(a[k], vs2[k], s2);
    }
    g_s1[r] = s1;
    g_s2[r] = s2;

    float4* zp = (float4*)(z + (size_t)r * 64);
    #pragma unroll
    for (int j4 = 0; j4 < 16; j4++) {
        float4 acc = bs[j4];
        #pragma unroll
        for (int k = 0; k < 16; k++) {
            float4 w = Ws[k * 16 + j4];
            acc.x = fmaf(a[k], w.x, acc.x);
            acc.y = fmaf(a[k], w.y, acc.y);
            acc.z = fmaf(a[k], w.z, acc.z);
            acc.w = fmaf(a[k], w.w, acc.w);
        }
        zp[j4] = acc;
    }
}

// -------- edge logits: s1[src] + s2[dst] + be --------
__global__ void k_logits(const int* __restrict__ ps, const int* __restrict__ pd,
                         const int* __restrict__ ns, const int* __restrict__ nd,
                         const float* __restrict__ be, float* __restrict__ out,
                         int P, int Ng, int n) {
    int i = blockIdx.x * blockDim.x + threadIdx.x;
    if (i >= P + Ng) return;
    unsigned s, d;
    if (i < P) { s = (unsigned)ps[i]; d = (unsigned)pd[i]; }
    else       { s = (unsigned)ns[i - P]; d = (unsigned)nd[i - P]; }
    float v = __ldg(be);
    if (s < (unsigned)n) v += g_s1[s];
    if (d < (unsigned)n) v += g_s2[d];
    out[i] = v;
}

extern "C" void kernel_launch(void* const* d_in, const int* in_sizes, int n_in,
                              void* d_out, int out_size) {
    const float* x  = (const float*)d_in[0];
    const float* W1 = (const float*)d_in[1];
    const float* b1 = (const float*)d_in[2];
    const float* W2 = (const float*)d_in[3];
    const float* b2 = (const float*)d_in[4];
    const float* We = (const float*)d_in[5];
    const float* be = (const float*)d_in[6];
    const int* ei = (const int*)d_in[7];   // edge_index as int32 [2, E]
    const int* pe = (const int*)d_in[8];   // pos_edge_index as int32 [2, P]
    const int* ne = (const int*)d_in[9];   // neg_edge_index as int32 [2, Ng]

    int n  = in_sizes[0] / 512;
    int E  = in_sizes[7] / 2;
    int P  = in_sizes[8] / 2;
    int Ng = in_sizes[9] / 2;

    float* z = (float*)d_out;                 // [n, 64]
    float* logits = z + (size_t)n * 64;       // [P + Ng]

    const int* src = ei;
    const int* dst = ei + E;

    int nb = (n + 255) / 256;
    int eb = (E + 255) / 256;
    int lb = (P + Ng + 255) / 256;

    k_pre<<<1, 32>>>(W2, b2, We);
    k_deg_init<<<nb, 256>>>(n);
    k_deg_acc<<<eb, 256>>>(dst, E, n);
    k_dinv<<<nb, 256>>>(n);
    k_gemm1<<<nb, 256>>>(x, W1, n);
    k_scatter1<<<eb, 256>>>(src, dst, E, n);
    k_relu<<<nb, 256>>>(b1, n);
    k_scatter2<<<eb, 256>>>(src, dst, E, n);
    k_out<<<nb, 256>>>(W2, b2, z, n);
    k_logits<<<lb, 256>>>(pe, pe + P, ne, ne + Ng, be, logits, P, Ng, n);
}

// round 5
// speedup vs baseline: 2.3429x; 1.3177x over previous
#include <cuda_runtime.h>

#define NMAX 100000
#define EMAX 3200000
#define NBLK ((NMAX + 255) / 256)   // 391

// -------- device scratch (no allocations allowed) --------
__device__ int   g_deg[NMAX];          // per-node in-degree (excl self-loop)
__device__ int   g_start[NMAX];        // CSR row start
__device__ int   g_cursor[NMAX];       // fill cursors
__device__ int   g_bsum[512];          // block sums for scan (NBLK <= 512)
__device__ int   g_adj[EMAX];          // CSR adjacency: src indices grouped by dst
__device__ float g_dinv[NMAX];         // 1/sqrt(deg+1)
__device__ __align__(16) float g_ht1[NMAX * 16];  // dinv * (x@W1)
__device__ __align__(16) float g_ht2[NMAX * 16];  // dinv * relu(agg1+b1)
__device__ float g_s1[NMAX];           // z . We[:64]
__device__ float g_s2[NMAX];           // z . We[64:]
__device__ float g_v1[16];             // W2 @ We[:64]
__device__ float g_v2[16];             // W2 @ We[64:]
__device__ float g_c1, g_c2;           // b2 . We halves

// -------- tiny precompute: fold W2/b2 into the edge head --------
__global__ void k_pre(const float* __restrict__ W2, const float* __restrict__ b2,
                      const float* __restrict__ We) {
    int t = threadIdx.x;
    if (t < 16) {
        float a = 0.f, b = 0.f;
        #pragma unroll
        for (int j = 0; j < 64; j++) {
            float w = W2[t * 64 + j];
            a += w * We[j];
            b += w * We[64 + j];
        }
        g_v1[t] = a;
        g_v2[t] = b;
    } else if (t == 16) {
        float a = 0.f, b = 0.f;
        #pragma unroll
        for (int j = 0; j < 64; j++) {
            a += b2[j] * We[j];
            b += b2[j] * We[64 + j];
        }
        g_c1 = a;
        g_c2 = b;
    }
}

// -------- CSR build --------
__global__ void k_deg_zero(int n) {
    int i = blockIdx.x * blockDim.x + threadIdx.x;
    if (i < n) g_deg[i] = 0;
}

__global__ void k_deg_acc(const int* __restrict__ dst, int E, int n) {
    int e = blockIdx.x * blockDim.x + threadIdx.x;
    if (e < E) {
        unsigned d = (unsigned)dst[e];
        if (d < (unsigned)n) atomicAdd(&g_deg[d], 1);
    }
}

// per-block exclusive scan of g_deg -> g_start (block-local), block totals -> g_bsum
__global__ void k_scan1(int n) {
    __shared__ int s[256];
    int tid = threadIdx.x;
    int i = blockIdx.x * 256 + tid;
    int v = (i < n) ? g_deg[i] : 0;
    s[tid] = v;
    __syncthreads();
    #pragma unroll
    for (int o = 1; o < 256; o <<= 1) {
        int t = (tid >= o) ? s[tid - o] : 0;
        __syncthreads();
        s[tid] += t;
        __syncthreads();
    }
    if (i < n) g_start[i] = s[tid] - v;            // exclusive within block
    if (tid == 255) g_bsum[blockIdx.x] = s[255];   // block total
}

// single-block exclusive scan of block sums (nb <= 512)
__global__ void k_scan2(int nb) {
    __shared__ int s[512];
    int tid = threadIdx.x;
    int v = (tid < nb) ? g_bsum[tid] : 0;
    s[tid] = v;
    __syncthreads();
    #pragma unroll
    for (int o = 1; o < 512; o <<= 1) {
        int t = (tid >= o) ? s[tid - o] : 0;
        __syncthreads();
        s[tid] += t;
        __syncthreads();
    }
    if (tid < nb) g_bsum[tid] = s[tid] - v;        // exclusive
}

// finalize: global row starts, cursors, dinv
__global__ void k_scan3(int n) {
    int i = blockIdx.x * blockDim.x + threadIdx.x;
    if (i >= n) return;
    int st = g_start[i] + g_bsum[blockIdx.x * 256 / 256 == 0 ? blockIdx.x : blockIdx.x]; // = g_bsum[blockIdx.x]
    st = g_start[i] + g_bsum[blockIdx.x];
    g_start[i] = st;
    g_cursor[i] = st;
    g_dinv[i] = rsqrtf((float)g_deg[i] + 1.0f);    // +1 = self-loop
}

__global__ void k_fill(const int* __restrict__ src, const int* __restrict__ dst,
                       int E, int n) {
    int e = blockIdx.x * blockDim.x + threadIdx.x;
    if (e >= E) return;
    unsigned s = (unsigned)src[e];
    unsigned d = (unsigned)dst[e];
    if (s >= (unsigned)n || d >= (unsigned)n) return;
    int slot = atomicAdd(&g_cursor[d], 1);
    g_adj[slot] = (int)s;
}

// -------- GEMM1: ht1 = dinv * (x @ W1) --------
__global__ void k_gemm1(const float* __restrict__ x, const float* __restrict__ W1, int n) {
    __shared__ float4 Wss[512 * 4];   // W1[k][4q..4q+3]  (32 KB)
    for (int i = threadIdx.x; i < 2048; i += blockDim.x)
        Wss[i] = ((const float4*)W1)[i];
    __syncthreads();

    int r = blockIdx.x * blockDim.x + threadIdx.x;
    if (r >= n) return;

    float acc[16];
    #pragma unroll
    for (int j = 0; j < 16; j++) acc[j] = 0.f;

    const float4* xr = (const float4*)(x + (size_t)r * 512);
    #pragma unroll 4
    for (int k4 = 0; k4 < 128; k4++) {
        float4 xv = __ldg(&xr[k4]);
        #pragma unroll
        for (int kk = 0; kk < 4; kk++) {
            float xs = ((const float*)&xv)[kk];
            int kbase = (k4 * 4 + kk) * 4;
            #pragma unroll
            for (int q = 0; q < 4; q++) {
                float4 w = Wss[kbase + q];
                acc[q * 4 + 0] = fmaf(xs, w.x, acc[q * 4 + 0]);
                acc[q * 4 + 1] = fmaf(xs, w.y, acc[q * 4 + 1]);
                acc[q * 4 + 2] = fmaf(xs, w.z, acc[q * 4 + 2]);
                acc[q * 4 + 3] = fmaf(xs, w.w, acc[q * 4 + 3]);
            }
        }
    }

    float di = g_dinv[r];
    float4* hp = (float4*)(g_ht1 + (size_t)r * 16);
    #pragma unroll
    for (int q = 0; q < 4; q++)
        hp[q] = make_float4(acc[q * 4 + 0] * di, acc[q * 4 + 1] * di,
                            acc[q * 4 + 2] * di, acc[q * 4 + 3] * di);
}

// -------- gather helper: 2 threads per node, each owns one 32B half-row --------
__device__ __forceinline__ void gather_half(const float* __restrict__ ht, int d, int half,
                                            float4& a0, float4& a1) {
    // init with self-loop term
    const float4* sp = (const float4*)(ht + (size_t)d * 16 + half * 8);
    a0 = __ldg(&sp[0]);
    a1 = __ldg(&sp[1]);
    int e = g_start[d];
    int end = e + g_deg[d];
    // 2 edges per iter for MLP
    for (; e + 1 < end; e += 2) {
        int s0 = __ldg(&g_adj[e]);
        int s1 = __ldg(&g_adj[e + 1]);
        const float4* p0 = (const float4*)(ht + (size_t)s0 * 16 + half * 8);
        const float4* p1 = (const float4*)(ht + (size_t)s1 * 16 + half * 8);
        float4 v00 = __ldg(&p0[0]), v01 = __ldg(&p0[1]);
        float4 v10 = __ldg(&p1[0]), v11 = __ldg(&p1[1]);
        a0.x += v00.x + v10.x; a0.y += v00.y + v10.y;
        a0.z += v00.z + v10.z; a0.w += v00.w + v10.w;
        a1.x += v01.x + v11.x; a1.y += v01.y + v11.y;
        a1.z += v01.z + v11.z; a1.w += v01.w + v11.w;
    }
    if (e < end) {
        int s0 = __ldg(&g_adj[e]);
        const float4* p0 = (const float4*)(ht + (size_t)s0 * 16 + half * 8);
        float4 v00 = __ldg(&p0[0]), v01 = __ldg(&p0[1]);
        a0.x += v00.x; a0.y += v00.y; a0.z += v00.z; a0.w += v00.w;
        a1.x += v01.x; a1.y += v01.y; a1.z += v01.z; a1.w += v01.w;
    }
}

// -------- gather layer 1: ht2 = dinv * relu(dinv*sum + b1) --------
__global__ void k_gather1(const float* __restrict__ b1, int n) {
    int t = blockIdx.x * blockDim.x + threadIdx.x;
    int d = t >> 1, half = t & 1;
    if (d >= n) return;
    float4 a0, a1;
    gather_half(g_ht1, d, half, a0, a1);
    float di = g_dinv[d];
    const float4* bb = (const float4*)b1 + half * 2;
    float4 b0 = __ldg(&bb[0]), b1q = __ldg(&bb[1]);
    float4 h0, h1;
    h0.x = fmaxf(fmaf(a0.x, di, b0.x), 0.f) * di;
    h0.y = fmaxf(fmaf(a0.y, di, b0.y), 0.f) * di;
    h0.z = fmaxf(fmaf(a0.z, di, b0.z), 0.f) * di;
    h0.w = fmaxf(fmaf(a0.w, di, b0.w), 0.f) * di;
    h1.x = fmaxf(fmaf(a1.x, di, b1q.x), 0.f) * di;
    h1.y = fmaxf(fmaf(a1.y, di, b1q.y), 0.f) * di;
    h1.z = fmaxf(fmaf(a1.z, di, b1q.z), 0.f) * di;
    h1.w = fmaxf(fmaf(a1.w, di, b1q.w), 0.f) * di;
    float4* op = (float4*)(g_ht2 + (size_t)d * 16 + half * 8);
    op[0] = h0;
    op[1] = h1;
}

// -------- gather layer 2 + fused epilogue: z, s1, s2 --------
__global__ void k_gather2(const float* __restrict__ W2, const float* __restrict__ b2,
                          float* __restrict__ z, int n) {
    __shared__ float4 Ws[16 * 16];   // W2[k] column-quads (4 KB)
    __shared__ float4 bs[16];
    __shared__ float vs1[16], vs2[16];
    for (int i = threadIdx.x; i < 256; i += blockDim.x)
        Ws[i] = ((const float4*)W2)[i];
    if (threadIdx.x < 16) {
        bs[threadIdx.x] = ((const float4*)b2)[threadIdx.x];
        vs1[threadIdx.x] = g_v1[threadIdx.x];
        vs2[threadIdx.x] = g_v2[threadIdx.x];
    }
    __syncthreads();

    int t = blockIdx.x * blockDim.x + threadIdx.x;
    int d = t >> 1, half = t & 1;
    bool valid = (d < n);
    int dd = valid ? d : 0;

    float4 a0, a1;
    gather_half(g_ht2, dd, half, a0, a1);
    float di = g_dinv[dd];

    float mine[8];
    mine[0] = a0.x * di; mine[1] = a0.y * di; mine[2] = a0.z * di; mine[3] = a0.w * di;
    mine[4] = a1.x * di; mine[5] = a1.y * di; mine[6] = a1.z * di; mine[7] = a1.w * di;

    // exchange halves with partner lane (lane ^ 1 handles same node, other half)
    float a[16];
    #pragma unroll
    for (int j = 0; j < 8; j++) {
        a[half * 8 + j] = mine[j];
        a[(1 - half) * 8 + j] = __shfl_xor_sync(0xffffffffu, mine[j], 1);
    }

    if (!valid) return;

    // head scalars (only half 0 writes)
    if (half == 0) {
        float s1 = g_c1, s2 = g_c2;
        #pragma unroll
        for (int k = 0; k < 16; k++) {
            s1 = fmaf(a[k], vs1[k], s1);
            s2 = fmaf(a[k], vs2[k], s2);
        }
        g_s1[d] = s1;
        g_s2[d] = s2;
    }

    // z columns [half*32, half*32+32)
    float4* zp = (float4*)(z + (size_t)d * 64) + half * 8;
    #pragma unroll
    for (int q = 0; q < 8; q++) {
        int j4 = half * 8 + q;
        float4 acc = bs[j4];
        #pragma unroll
        for (int k = 0; k < 16; k++) {
            float4 w = Ws[k * 16 + j4];
            acc.x = fmaf(a[k], w.x, acc.x);
            acc.y = fmaf(a[k], w.y, acc.y);
            acc.z = fmaf(a[k], w.z, acc.z);
            acc.w = fmaf(a[k], w.w, acc.w);
        }
        zp[q] = acc;
    }
}

// -------- edge logits: s1[src] + s2[dst] + be --------
__global__ void k_logits(const int* __restrict__ ps, const int* __restrict__ pd,
                         const int* __restrict__ ns, const int* __restrict__ nd,
                         const float* __restrict__ be, float* __restrict__ out,
                         int P, int Ng, int n) {
    int i = blockIdx.x * blockDim.x + threadIdx.x;
    if (i >= P + Ng) return;
    unsigned s, d;
    if (i < P) { s = (unsigned)ps[i]; d = (unsigned)pd[i]; }
    else       { s = (unsigned)ns[i - P]; d = (unsigned)nd[i - P]; }
    float v = __ldg(be);
    if (s < (unsigned)n) v += g_s1[s];
    if (d < (unsigned)n) v += g_s2[d];
    out[i] = v;
}

extern "C" void kernel_launch(void* const* d_in, const int* in_sizes, int n_in,
                              void* d_out, int out_size) {
    const float* x  = (const float*)d_in[0];
    const float* W1 = (const float*)d_in[1];
    const float* b1 = (const float*)d_in[2];
    const float* W2 = (const float*)d_in[3];
    const float* b2 = (const float*)d_in[4];
    const float* We = (const float*)d_in[5];
    const float* be = (const float*)d_in[6];
    const int* ei = (const int*)d_in[7];   // edge_index int32 [2, E]
    const int* pe = (const int*)d_in[8];   // pos_edge_index int32 [2, P]
    const int* ne = (const int*)d_in[9];   // neg_edge_index int32 [2, Ng]

    int n  = in_sizes[0] / 512;
    int E  = in_sizes[7] / 2;
    int P  = in_sizes[8] / 2;
    int Ng = in_sizes[9] / 2;

    float* z = (float*)d_out;                 // [n, 64]
    float* logits = z + (size_t)n * 64;       // [P + Ng]

    const int* src = ei;
    const int* dst = ei + E;

    int nb  = (n + 255) / 256;
    int eb  = (E + 255) / 256;
    int gb  = (2 * n + 255) / 256;
    int lb  = (P + Ng + 255) / 256;

    k_pre<<<1, 32>>>(W2, b2, We);
    k_deg_zero<<<nb, 256>>>(n);
    k_deg_acc<<<eb, 256>>>(dst, E, n);
    k_scan1<<<nb, 256>>>(n);
    k_scan2<<<1, 512>>>(nb);
    k_scan3<<<nb, 256>>>(n);
    k_fill<<<eb, 256>>>(src, dst, E, n);
    k_gemm1<<<nb, 256>>>(x, W1, n);
    k_gather1<<<gb, 256>>>(b1, n);
    k_gather2<<<gb, 256>>>(W2, b2, z, n);
    k_logits<<<lb, 256>>>(pe, pe + P, ne, ne + Ng, be, logits, P, Ng, n);
}

// round 6
// speedup vs baseline: 2.7036x; 1.1539x over previous
#include <cuda_runtime.h>

#define NMAX 100000
#define EMAX 3200000

// -------- device scratch (no allocations allowed) --------
__device__ int   g_deg[NMAX];          // per-node in-degree (excl self-loop)
__device__ int   g_start[NMAX];        // CSR row start
__device__ int   g_cursor[NMAX];       // fill cursors
__device__ int   g_bsum[512];          // block sums for scan (NBLK <= 512)
__device__ int   g_adj[EMAX];          // CSR adjacency: src indices grouped by dst
__device__ float g_dinv[NMAX];         // 1/sqrt(deg+1)
__device__ __align__(16) float g_ht1[NMAX * 16];  // h = x@W1 (raw), then dinv*h
__device__ __align__(16) float g_ht2[NMAX * 16];  // dinv * relu(agg1+b1)
__device__ float g_s1[NMAX];           // z . We[:64]
__device__ float g_s2[NMAX];           // z . We[64:]
__device__ float g_v1[16];             // W2 @ We[:64]
__device__ float g_v2[16];             // W2 @ We[64:]
__device__ float g_c1, g_c2;           // b2 . We halves

// -------- zero degrees + fold W2/b2 into the edge head (merged) --------
__global__ void k_predeg(const float* __restrict__ W2, const float* __restrict__ b2,
                         const float* __restrict__ We, int n) {
    int i = blockIdx.x * blockDim.x + threadIdx.x;
    if (i < n) g_deg[i] = 0;
    if (blockIdx.x == 0) {
        int t = threadIdx.x;
        if (t < 16) {
            float a = 0.f, b = 0.f;
            #pragma unroll
            for (int j = 0; j < 64; j++) {
                float w = W2[t * 64 + j];
                a += w * We[j];
                b += w * We[64 + j];
            }
            g_v1[t] = a;
            g_v2[t] = b;
        } else if (t == 16) {
            float a = 0.f, b = 0.f;
            #pragma unroll
            for (int j = 0; j < 64; j++) {
                a += b2[j] * We[j];
                b += b2[j] * We[64 + j];
            }
            g_c1 = a;
            g_c2 = b;
        }
    }
}

__global__ void k_deg_acc(const int* __restrict__ dst, int E, int n) {
    int e = blockIdx.x * blockDim.x + threadIdx.x;
    if (e < E) {
        unsigned d = (unsigned)dst[e];
        if (d < (unsigned)n) atomicAdd(&g_deg[d], 1);
    }
}

// per-block exclusive scan of g_deg -> g_start (block-local), block totals -> g_bsum
__global__ void k_scan1(int n) {
    __shared__ int s[256];
    int tid = threadIdx.x;
    int i = blockIdx.x * 256 + tid;
    int v = (i < n) ? g_deg[i] : 0;
    s[tid] = v;
    __syncthreads();
    #pragma unroll
    for (int o = 1; o < 256; o <<= 1) {
        int t = (tid >= o) ? s[tid - o] : 0;
        __syncthreads();
        s[tid] += t;
        __syncthreads();
    }
    if (i < n) g_start[i] = s[tid] - v;            // exclusive within block
    if (tid == 255) g_bsum[blockIdx.x] = s[255];   // block total
}

// single-block exclusive scan of block sums (nb <= 512)
__global__ void k_scan2(int nb) {
    __shared__ int s[512];
    int tid = threadIdx.x;
    int v = (tid < nb) ? g_bsum[tid] : 0;
    s[tid] = v;
    __syncthreads();
    #pragma unroll
    for (int o = 1; o < 512; o <<= 1) {
        int t = (tid >= o) ? s[tid - o] : 0;
        __syncthreads();
        s[tid] += t;
        __syncthreads();
    }
    if (tid < nb) g_bsum[tid] = s[tid] - v;        // exclusive
}

// finalize: global row starts, cursors, dinv
__global__ void k_scan3(int n) {
    int i = blockIdx.x * blockDim.x + threadIdx.x;
    if (i >= n) return;
    int st = g_start[i] + g_bsum[blockIdx.x];
    g_start[i] = st;
    g_cursor[i] = st;
    g_dinv[i] = rsqrtf((float)g_deg[i] + 1.0f);    // +1 = self-loop
}

__global__ void k_fill(const int* __restrict__ src, const int* __restrict__ dst,
                       int E, int n) {
    int e = blockIdx.x * blockDim.x + threadIdx.x;
    if (e >= E) return;
    unsigned s = (unsigned)src[e];
    unsigned d = (unsigned)dst[e];
    if (s >= (unsigned)n || d >= (unsigned)n) return;
    int slot = atomicAdd(&g_cursor[d], 1);
    g_adj[slot] = (int)s;
}

// -------- GEMM1: ht1 = x @ W1 (raw; dinv applied later in k_scale) --------
__global__ void k_gemm1(const float* __restrict__ x, const float* __restrict__ W1, int n) {
    __shared__ float4 Wss[512 * 4];   // W1[k][4q..4q+3]  (32 KB)
    for (int i = threadIdx.x; i < 2048; i += blockDim.x)
        Wss[i] = ((const float4*)W1)[i];
    __syncthreads();

    int r = blockIdx.x * blockDim.x + threadIdx.x;
    if (r >= n) return;

    float acc[16];
    #pragma unroll
    for (int j = 0; j < 16; j++) acc[j] = 0.f;

    const float4* xr = (const float4*)(x + (size_t)r * 512);
    #pragma unroll 4
    for (int k4 = 0; k4 < 128; k4++) {
        float4 xv = __ldg(&xr[k4]);
        #pragma unroll
        for (int kk = 0; kk < 4; kk++) {
            float xs = ((const float*)&xv)[kk];
            int kbase = (k4 * 4 + kk) * 4;
            #pragma unroll
            for (int q = 0; q < 4; q++) {
                float4 w = Wss[kbase + q];
                acc[q * 4 + 0] = fmaf(xs, w.x, acc[q * 4 + 0]);
                acc[q * 4 + 1] = fmaf(xs, w.y, acc[q * 4 + 1]);
                acc[q * 4 + 2] = fmaf(xs, w.z, acc[q * 4 + 2]);
                acc[q * 4 + 3] = fmaf(xs, w.w, acc[q * 4 + 3]);
            }
        }
    }

    float4* hp = (float4*)(g_ht1 + (size_t)r * 16);
    #pragma unroll
    for (int q = 0; q < 4; q++)
        hp[q] = make_float4(acc[q * 4 + 0], acc[q * 4 + 1],
                            acc[q * 4 + 2], acc[q * 4 + 3]);
}

// -------- scale: ht1 *= dinv (join point after gemm1 || CSR build) --------
__global__ void k_scale(int n) {
    int i = blockIdx.x * blockDim.x + threadIdx.x;
    if (i >= n) return;
    float di = g_dinv[i];
    float4* p = (float4*)(g_ht1 + (size_t)i * 16);
    #pragma unroll
    for (int q = 0; q < 4; q++) {
        float4 v = p[q];
        p[q] = make_float4(v.x * di, v.y * di, v.z * di, v.w * di);
    }
}

// -------- gather helper: 2 threads per node, each owns one 32B half-row --------
__device__ __forceinline__ void gather_half(const float* __restrict__ ht, int d, int half,
                                            float4& a0, float4& a1) {
    // init with self-loop term
    const float4* sp = (const float4*)(ht + (size_t)d * 16 + half * 8);
    a0 = __ldg(&sp[0]);
    a1 = __ldg(&sp[1]);
    int e = g_start[d];
    int end = e + g_deg[d];
    // 4 edges per iter: 8 independent 16B loads in flight
    for (; e + 3 < end; e += 4) {
        int s0 = __ldg(&g_adj[e]);
        int s1 = __ldg(&g_adj[e + 1]);
        int s2 = __ldg(&g_adj[e + 2]);
        int s3 = __ldg(&g_adj[e + 3]);
        const float4* p0 = (const float4*)(ht + (size_t)s0 * 16 + half * 8);
        const float4* p1 = (const float4*)(ht + (size_t)s1 * 16 + half * 8);
        const float4* p2 = (const float4*)(ht + (size_t)s2 * 16 + half * 8);
        const float4* p3 = (const float4*)(ht + (size_t)s3 * 16 + half * 8);
        float4 v00 = __ldg(&p0[0]), v01 = __ldg(&p0[1]);
        float4 v10 = __ldg(&p1[0]), v11 = __ldg(&p1[1]);
        float4 v20 = __ldg(&p2[0]), v21 = __ldg(&p2[1]);
        float4 v30 = __ldg(&p3[0]), v31 = __ldg(&p3[1]);
        a0.x += (v00.x + v10.x) + (v20.x + v30.x);
        a0.y += (v00.y + v10.y) + (v20.y + v30.y);
        a0.z += (v00.z + v10.z) + (v20.z + v30.z);
        a0.w += (v00.w + v10.w) + (v20.w + v30.w);
        a1.x += (v01.x + v11.x) + (v21.x + v31.x);
        a1.y += (v01.y + v11.y) + (v21.y + v31.y);
        a1.z += (v01.z + v11.z) + (v21.z + v31.z);
        a1.w += (v01.w + v11.w) + (v21.w + v31.w);
    }
    for (; e < end; e++) {
        int s0 = __ldg(&g_adj[e]);
        const float4* p0 = (const float4*)(ht + (size_t)s0 * 16 + half * 8);
        float4 v00 = __ldg(&p0[0]), v01 = __ldg(&p0[1]);
        a0.x += v00.x; a0.y += v00.y; a0.z += v00.z; a0.w += v00.w;
        a1.x += v01.x; a1.y += v01.y; a1.z += v01.z; a1.w += v01.w;
    }
}

// -------- gather layer 1: ht2 = dinv * relu(dinv*sum + b1) --------
__global__ void k_gather1(const float* __restrict__ b1, int n) {
    int t = blockIdx.x * blockDim.x + threadIdx.x;
    int d = t >> 1, half = t & 1;
    if (d >= n) return;
    float4 a0, a1;
    gather_half(g_ht1, d, half, a0, a1);
    float di = g_dinv[d];
    const float4* bb = (const float4*)b1 + half * 2;
    float4 b0 = __ldg(&bb[0]), b1q = __ldg(&bb[1]);
    float4 h0, h1;
    h0.x = fmaxf(fmaf(a0.x, di, b0.x), 0.f) * di;
    h0.y = fmaxf(fmaf(a0.y, di, b0.y), 0.f) * di;
    h0.z = fmaxf(fmaf(a0.z, di, b0.z), 0.f) * di;
    h0.w = fmaxf(fmaf(a0.w, di, b0.w), 0.f) * di;
    h1.x = fmaxf(fmaf(a1.x, di, b1q.x), 0.f) * di;
    h1.y = fmaxf(fmaf(a1.y, di, b1q.y), 0.f) * di;
    h1.z = fmaxf(fmaf(a1.z, di, b1q.z), 0.f) * di;
    h1.w = fmaxf(fmaf(a1.w, di, b1q.w), 0.f) * di;
    float4* op = (float4*)(g_ht2 + (size_t)d * 16 + half * 8);
    op[0] = h0;
    op[1] = h1;
}

// -------- gather layer 2 + fused epilogue: z, s1, s2 --------
__global__ void k_gather2(const float* __restrict__ W2, const float* __restrict__ b2,
                          float* __restrict__ z, int n) {
    __shared__ float4 Ws[16 * 16];   // W2[k] column-quads (4 KB)
    __shared__ float4 bs[16];
    __shared__ float vs1[16], vs2[16];
    for (int i = threadIdx.x; i < 256; i += blockDim.x)
        Ws[i] = ((const float4*)W2)[i];
    if (threadIdx.x < 16) {
        bs[threadIdx.x] = ((const float4*)b2)[threadIdx.x];
        vs1[threadIdx.x] = g_v1[threadIdx.x];
        vs2[threadIdx.x] = g_v2[threadIdx.x];
    }
    __syncthreads();

    int t = blockIdx.x * blockDim.x + threadIdx.x;
    int d = t >> 1, half = t & 1;
    bool valid = (d < n);
    int dd = valid ? d : 0;

    float4 a0, a1;
    gather_half(g_ht2, dd, half, a0, a1);
    float di = g_dinv[dd];

    float mine[8];
    mine[0] = a0.x * di; mine[1] = a0.y * di; mine[2] = a0.z * di; mine[3] = a0.w * di;
    mine[4] = a1.x * di; mine[5] = a1.y * di; mine[6] = a1.z * di; mine[7] = a1.w * di;

    // exchange halves with partner lane (lane ^ 1 handles same node, other half)
    float a[16];
    #pragma unroll
    for (int j = 0; j < 8; j++) {
        a[half * 8 + j] = mine[j];
        a[(1 - half) * 8 + j] = __shfl_xor_sync(0xffffffffu, mine[j], 1);
    }

    if (!valid) return;

    // head scalars (only half 0 writes)
    if (half == 0) {
        float s1 = g_c1, s2 = g_c2;
        #pragma unroll
        for (int k = 0; k < 16; k++) {
            s1 = fmaf(a[k], vs1[k], s1);
            s2 = fmaf(a[k], vs2[k], s2);
        }
        g_s1[d] = s1;
        g_s2[d] = s2;
    }

    // z columns [half*32, half*32+32)
    float4* zp = (float4*)(z + (size_t)d * 64) + half * 8;
    #pragma unroll
    for (int q = 0; q < 8; q++) {
        int j4 = half * 8 + q;
        float4 acc = bs[j4];
        #pragma unroll
        for (int k = 0; k < 16; k++) {
            float4 w = Ws[k * 16 + j4];
            acc.x = fmaf(a[k], w.x, acc.x);
            acc.y = fmaf(a[k], w.y, acc.y);
            acc.z = fmaf(a[k], w.z, acc.z);
            acc.w = fmaf(a[k], w.w, acc.w);
        }
        zp[q] = acc;
    }
}

// -------- edge logits: s1[src] + s2[dst] + be --------
__global__ void k_logits(const int* __restrict__ ps, const int* __restrict__ pd,
                         const int* __restrict__ ns, const int* __restrict__ nd,
                         const float* __restrict__ be, float* __restrict__ out,
                         int P, int Ng, int n) {
    int i = blockIdx.x * blockDim.x + threadIdx.x;
    if (i >= P + Ng) return;
    unsigned s, d;
    if (i < P) { s = (unsigned)ps[i]; d = (unsigned)pd[i]; }
    else       { s = (unsigned)ns[i - P]; d = (unsigned)nd[i - P]; }
    float v = __ldg(be);
    if (s < (unsigned)n) v += g_s1[s];
    if (d < (unsigned)n) v += g_s2[d];
    out[i] = v;
}

extern "C" void kernel_launch(void* const* d_in, const int* in_sizes, int n_in,
                              void* d_out, int out_size) {
    const float* x  = (const float*)d_in[0];
    const float* W1 = (const float*)d_in[1];
    const float* b1 = (const float*)d_in[2];
    const float* W2 = (const float*)d_in[3];
    const float* b2 = (const float*)d_in[4];
    const float* We = (const float*)d_in[5];
    const float* be = (const float*)d_in[6];
    const int* ei = (const int*)d_in[7];   // edge_index int32 [2, E]
    const int* pe = (const int*)d_in[8];   // pos_edge_index int32 [2, P]
    const int* ne = (const int*)d_in[9];   // neg_edge_index int32 [2, Ng]

    int n  = in_sizes[0] / 512;
    int E  = in_sizes[7] / 2;
    int P  = in_sizes[8] / 2;
    int Ng = in_sizes[9] / 2;

    float* z = (float*)d_out;                 // [n, 64]
    float* logits = z + (size_t)n * 64;       // [P + Ng]

    const int* src = ei;
    const int* dst = ei + E;

    int nb  = (n + 255) / 256;
    int eb  = (E + 255) / 256;
    int gb  = (2 * n + 255) / 256;
    int lb  = (P + Ng + 255) / 256;

    // One-time stream/event setup (outside capture: first call is uncaptured).
    static cudaStream_t s1 = nullptr;
    static cudaEvent_t evFork = nullptr, evJoin = nullptr;
    if (s1 == nullptr) {
        cudaStreamCreateWithFlags(&s1, cudaStreamNonBlocking);
        cudaEventCreateWithFlags(&evFork, cudaEventDisableTiming);
        cudaEventCreateWithFlags(&evJoin, cudaEventDisableTiming);
    }

    // Fork: GEMM1 (independent of CSR build) runs on s1.
    cudaEventRecord(evFork, 0);
    cudaStreamWaitEvent(s1, evFork, 0);
    k_gemm1<<<nb, 256, 0, s1>>>(x, W1, n);
    cudaEventRecord(evJoin, s1);

    // Main stream: CSR build chain.
    k_predeg<<<nb, 256>>>(W2, b2, We, n);
    k_deg_acc<<<eb, 256>>>(dst, E, n);
    k_scan1<<<nb, 256>>>(n);
    k_scan2<<<1, 512>>>(nb);
    k_scan3<<<nb, 256>>>(n);
    k_fill<<<eb, 256>>>(src, dst, E, n);

    // Join: scale needs both gemm1 (h) and scan3 (dinv).
    cudaStreamWaitEvent(0, evJoin, 0);
    k_scale<<<nb, 256>>>(n);
    k_gather1<<<gb, 256>>>(b1, n);
    k_gather2<<<gb, 256>>>(W2, b2, z, n);
    k_logits<<<lb, 256>>>(pe, pe + P, ne, ne + Ng, be, logits, P, Ng, n);
}